// round 14
// baseline (speedup 1.0000x reference)
#include <cuda_runtime.h>
#include <cuda_bf16.h>
#include <cstdint>

#define B_ROWS 4096
#define M_COLS 16384
#define D_DIM  512
#define N_BMU  16
#define CAP    256

#define C1 ((float)(2.0 * 1e-6))
#define C2 ((float)(512.0 * (1e-6 * 1e-6)))
#define FINF __int_as_float(0x7f800000)
#define MAXKEY 0xFFFFFFFFFFFFFFFFull

#define NBLK (M_COLS / 128)      // 128 rowmin blocks per row
#define NSTG (D_DIM / 32)        // 16 k-stages
#define SMEM_GEMM 65536          // 4 stages x (8KB A + 8KB B)
#define NMT (B_ROWS / 128)       // 32 mtiles

// Scratch (no cudaMalloc allowed)
__device__ unsigned g_approxh[(size_t)B_ROWS * M_COLS / 2];   // bf16x2, 128MB
__device__ float g_rowmin[(size_t)B_ROWS * NBLK];
__device__ float g_w2[M_COLS];
__device__ float g_sw[M_COLS];
__device__ float g_x2[B_ROWS];
__device__ float g_sx[B_ROWS];
__device__ float g_wT[(size_t)M_COLS * D_DIM];
__device__ uint4 g_xfrag[(B_ROWS / 16) * (D_DIM / 16) * 32];
__device__ uint2 g_wfrag[(M_COLS / 8) * (D_DIM / 16) * 32];
__device__ int   g_cand[(size_t)B_ROWS * CAP];
__device__ int   g_ccnt[B_ROWS];
__device__ int   g_mdone[NMT];
__device__ int   g_maxx2_bits;
__device__ int   g_maxw2_bits;

__device__ __forceinline__ unsigned smem_u32(const void* p) {
    return (unsigned)__cvta_generic_to_shared(p);
}
#define CP_ASYNC16(dst, src) \
    asm volatile("cp.async.cg.shared.global [%0], [%1], 16;\n" :: "r"(dst), "l"(src))
#define CP_COMMIT() asm volatile("cp.async.commit_group;\n" ::)
#define CP_WAIT(n)  asm volatile("cp.async.wait_group %0;\n" :: "n"(n))

__device__ __forceinline__ unsigned pack_bf16(float lo, float hi) {
    __nv_bfloat162 h = __floats2bfloat162_rn(lo, hi);
    return *reinterpret_cast<unsigned*>(&h);
}
__device__ __forceinline__ float2 unpack_bf16(unsigned u) {
    __nv_bfloat162 h = *reinterpret_cast<__nv_bfloat162*>(&u);
    return __bfloat1622float2(h);
}
__device__ __forceinline__ void mma_bf16(float c[4], unsigned a0, unsigned a1,
                                         unsigned a2, unsigned a3,
                                         unsigned b0, unsigned b1) {
    asm volatile(
        "mma.sync.aligned.m16n8k16.row.col.f32.bf16.bf16.f32 "
        "{%0,%1,%2,%3}, {%4,%5,%6,%7}, {%8,%9}, {%0,%1,%2,%3};"
        : "+f"(c[0]), "+f"(c[1]), "+f"(c[2]), "+f"(c[3])
        : "r"(a0), "r"(a1), "r"(a2), "r"(a3), "r"(b0), "r"(b1));
}

// ---------------------------------------------------------------------------
// Column stats (FROZEN): fp64 accumulation of fp32-rounded squares. +max
// Also resets the per-mtile completion counters for the fused collect.
// ---------------------------------------------------------------------------
__global__ __launch_bounds__(256)
void wstats_kernel(const float* __restrict__ w) {
    if (threadIdx.x == 0 && blockIdx.x < NMT) g_mdone[blockIdx.x] = 0;
    int m = blockIdx.x * blockDim.x + threadIdx.x;
    if (m >= M_COLS) return;
    double w2 = 0.0, sw = 0.0;
    for (int d = 0; d < D_DIM; ++d) {
        float v = w[(size_t)d * M_COLS + m];
        w2 += (double)__fmul_rn(v, v);
        sw += (double)v;
    }
    float w2f = (float)w2;
    g_w2[m] = w2f;
    g_sw[m] = (float)sw;
    atomicMax(&g_maxw2_bits, __float_as_int(w2f));
}

// ---------------------------------------------------------------------------
// Row stats (FROZEN): fp64 accumulation per row. +max
// ---------------------------------------------------------------------------
__global__ __launch_bounds__(256)
void xstats_kernel(const float* __restrict__ x) {
    const int row = blockIdx.x * 8 + (threadIdx.x >> 5);
    const int lane = threadIdx.x & 31;
    if (row >= B_ROWS) return;
    const float* xr = x + (size_t)row * D_DIM;

    double p2 = 0.0, p1 = 0.0;
    for (int i = lane; i < D_DIM; i += 32) {
        float v = xr[i];
        p2 += (double)__fmul_rn(v, v);
        p1 += (double)v;
    }
    #pragma unroll
    for (int off = 16; off; off >>= 1) {
        p2 += __shfl_xor_sync(0xffffffffu, p2, off);
        p1 += __shfl_xor_sync(0xffffffffu, p1, off);
    }
    if (lane == 0) {
        float x2f = (float)p2;
        g_x2[row] = x2f;
        g_sx[row] = (float)p1;
        atomicMax(&g_maxx2_bits, __float_as_int(x2f));
    }
}

// ---------------------------------------------------------------------------
// Converters (fragment layouts verified in R9)
// ---------------------------------------------------------------------------
__global__ __launch_bounds__(256)
void convert_x_kernel(const float* __restrict__ x) {
    int idx = blockIdx.x * blockDim.x + threadIdx.x;
    int lane = idx & 31;
    int kt = (idx >> 5) % (D_DIM / 16);
    int mt = (idx >> 5) / (D_DIM / 16);
    if (mt >= B_ROWS / 16) return;
    int r = mt * 16 + (lane >> 2);
    int c = kt * 16 + (lane & 3) * 2;
    const float* base = x + (size_t)r * D_DIM + c;
    uint4 o;
    o.x = pack_bf16(base[0], base[1]);
    o.y = pack_bf16(base[8 * D_DIM], base[8 * D_DIM + 1]);
    o.z = pack_bf16(base[8], base[9]);
    o.w = pack_bf16(base[8 * D_DIM + 8], base[8 * D_DIM + 9]);
    g_xfrag[idx] = o;
}

__global__ __launch_bounds__(256)
void convert_w_kernel(const float* __restrict__ w) {
    int idx = blockIdx.x * blockDim.x + threadIdx.x;
    int lane = idx & 31;
    int kt = (idx >> 5) % (D_DIM / 16);
    int nt = (idx >> 5) / (D_DIM / 16);
    if (nt >= M_COLS / 8) return;
    int k = kt * 16 + (lane & 3) * 2;
    int n = nt * 8 + (lane >> 2);
    const float* base = w + (size_t)k * M_COLS + n;
    uint2 o;
    o.x = pack_bf16(base[0], base[M_COLS]);
    o.y = pack_bf16(base[8 * (size_t)M_COLS], base[9 * (size_t)M_COLS]);
    g_wfrag[idx] = o;
}

// ---------------------------------------------------------------------------
// Transpose w -> wT[m][d] (fp32, for exact rescore)
// ---------------------------------------------------------------------------
__global__ __launch_bounds__(256)
void transpose_w_kernel(const float* __restrict__ w) {
    __shared__ float tile[32][33];
    int bx = blockIdx.x, by = blockIdx.y;
    int tx = threadIdx.x, ty = threadIdx.y;
    #pragma unroll
    for (int i = 0; i < 4; ++i)
        tile[ty + i * 8][tx] = w[(size_t)(by * 32 + ty + i * 8) * M_COLS + bx * 32 + tx];
    __syncthreads();
    #pragma unroll
    for (int i = 0; i < 4; ++i)
        g_wT[(size_t)(bx * 32 + ty + i * 8) * D_DIM + by * 32 + tx] = tile[tx][ty + i * 8];
}

// ---------------------------------------------------------------------------
// Prune GEMM (R12 mainloop, at the legacy-HMMA wall) + FUSED collect:
// the last CTA finishing an mtile row-block runs the candidate collect for
// those 128 rows while the data is L2-hot (canonical threadfence/atomic
// last-block pattern). Collect logic byte-identical to R12's.
// ---------------------------------------------------------------------------
__global__ __launch_bounds__(256, 2)
void prune_gemm_kernel() {
    extern __shared__ char smem[];
    uint4* As = (uint4*)smem;                     // [4][512]
    uint2* Bs = (uint2*)(smem + 32768);           // [4][1024]

    const int tid = threadIdx.x;
    const int lane = tid & 31;
    const int wid = tid >> 5;
    const int wm = wid >> 2;          // 0..1
    const int wn = wid & 3;           // 0..3
    const int ntile = blockIdx.x, mtile = blockIdx.y;
    const int mtBase = mtile * 8;     // m16 tiles
    const int ntBase = ntile * 16;    // n8 tiles

    float c[4][4][4];
    #pragma unroll
    for (int i = 0; i < 4; ++i)
        #pragma unroll
        for (int j = 0; j < 4; ++j)
            #pragma unroll
            for (int r = 0; r < 4; ++r) c[i][j][r] = 0.f;

    auto issue = [&](int s) {
        const int buf = s & 3;
        #pragma unroll
        for (int r = 0; r < 2; ++r) {       // A: 512 x 16B
            int ch = tid + r * 256;
            int mt = ch >> 6, kt = (ch >> 5) & 1, ln = ch & 31;
            const uint4* src = g_xfrag +
                ((size_t)(mtBase + mt) * (D_DIM / 16) + s * 2 + kt) * 32 + ln;
            CP_ASYNC16(smem_u32(&As[buf * 512 + ch]), src);
        }
        #pragma unroll
        for (int r = 0; r < 2; ++r) {       // B: 512 x 16B (uint2 pairs)
            int cb = tid + r * 256;
            int nt = cb >> 5, kt = (cb >> 4) & 1, lp = cb & 15;
            const uint2* src = g_wfrag +
                ((size_t)(ntBase + nt) * (D_DIM / 16) + s * 2 + kt) * 32 + lp * 2;
            CP_ASYNC16(smem_u32(&Bs[buf * 1024 + ((nt * 2 + kt) * 32 + lp * 2)]), src);
        }
        CP_COMMIT();
    };

    issue(0); issue(1); issue(2);

    for (int s = 0; s < NSTG; ++s) {
        if (s <= 13)      { CP_WAIT(2); }
        else if (s == 14) { CP_WAIT(1); }
        else              { CP_WAIT(0); }
        __syncthreads();
        if (s + 3 < NSTG) issue(s + 3);

        const int buf = s & 3;
        #pragma unroll
        for (int kt = 0; kt < 2; ++kt) {
            uint4 a[4];
            #pragma unroll
            for (int i = 0; i < 4; ++i)
                a[i] = As[buf * 512 + ((wm * 4 + i) * 2 + kt) * 32 + lane];
            uint2 b[4];
            #pragma unroll
            for (int j = 0; j < 4; ++j)
                b[j] = Bs[buf * 1024 + ((wn * 4 + j) * 2 + kt) * 32 + lane];
            #pragma unroll
            for (int i = 0; i < 4; ++i)
                #pragma unroll
                for (int j = 0; j < 4; ++j)
                    mma_bf16(c[i][j], a[i].x, a[i].y, a[i].z, a[i].w, b[j].x, b[j].y);
        }
    }
    __syncthreads();   // all MMAs done; reuse smem for epilogue staging

    unsigned* st = (unsigned*)smem;             // [128][68] u32 (bf16x2)
    float* srm = (float*)(smem + 128 * 68 * 4); // [128]
    if (tid < 128) srm[tid] = FINF;
    __syncthreads();

    #pragma unroll
    for (int i = 0; i < 4; ++i) {
        int rl = wm * 64 + i * 16 + (lane >> 2);       // local rows rl, rl+8
        int gr = mtile * 128 + rl;
        float x2a = g_x2[gr], x2b = g_x2[gr + 8];
        float rmin0 = FINF, rmin1 = FINF;
        #pragma unroll
        for (int j = 0; j < 4; ++j) {
            int gc = ntile * 128 + wn * 32 + j * 8 + (lane & 3) * 2;
            float w2a = g_w2[gc], w2b = g_w2[gc + 1];
            float s0 = x2a + w2a - 2.f * c[i][j][0];
            float s1 = x2a + w2b - 2.f * c[i][j][1];
            float s2 = x2b + w2a - 2.f * c[i][j][2];
            float s3 = x2b + w2b - 2.f * c[i][j][3];
            int stcol = wn * 16 + j * 4 + (lane & 3);
            st[rl * 68 + stcol]       = pack_bf16(s0, s1);
            st[(rl + 8) * 68 + stcol] = pack_bf16(s2, s3);
            rmin0 = fminf(rmin0, fminf(s0, s1));
            rmin1 = fminf(rmin1, fminf(s2, s3));
        }
        rmin0 = fminf(rmin0, __shfl_xor_sync(0xffffffffu, rmin0, 1));
        rmin0 = fminf(rmin0, __shfl_xor_sync(0xffffffffu, rmin0, 2));
        rmin1 = fminf(rmin1, __shfl_xor_sync(0xffffffffu, rmin1, 1));
        rmin1 = fminf(rmin1, __shfl_xor_sync(0xffffffffu, rmin1, 2));
        if ((lane & 3) == 0) {
            atomicMin((int*)&srm[rl],     __float_as_int(fmaxf(rmin0, 0.f)));
            atomicMin((int*)&srm[rl + 8], __float_as_int(fmaxf(rmin1, 0.f)));
        }
    }
    __syncthreads();

    // Coalesced stores: each row = 64 u32 = 16 uint4; 16 threads per row.
    #pragma unroll
    for (int p = 0; p < 8; ++p) {
        int rl = p * 16 + (tid >> 4);
        uint4 v = *(uint4*)&st[rl * 68 + (tid & 15) * 4];
        *(uint4*)(g_approxh + (size_t)(mtile * 128 + rl) * (M_COLS / 2) +
                  ntile * 64 + (tid & 15) * 4) = v;
    }
    if (tid < 128)
        g_rowmin[(size_t)(mtile * 128 + tid) * NBLK + ntile] = srm[tid];

    // ---- fused collect: last CTA of this mtile does 128 rows ----
    __threadfence();
    __syncthreads();
    __shared__ int s_last;
    if (tid == 0)
        s_last = (atomicAdd(&g_mdone[mtile], 1) == NBLK - 1);
    __syncthreads();
    if (!s_last) return;

    float mx = __int_as_float(g_maxx2_bits);
    float mw = __int_as_float(g_maxw2_bits);
    float margin = 0.017f * sqrtf(mx * mw) + 0.25f;

    for (int rr = 0; rr < 16; ++rr) {              // 8 warps x 16 rows = 128
        const int q = mtile * 128 + wid * 16 + rr;
        const float* rm = g_rowmin + (size_t)q * NBLK;

        float lmin = fminf(fminf(rm[lane], rm[lane + 32]),
                           fminf(rm[lane + 64], rm[lane + 96]));
        float cur = lmin, tau = FINF;
        #pragma unroll
        for (int r = 0; r < N_BMU; ++r) {
            float mn = cur;
            #pragma unroll
            for (int o = 16; o; o >>= 1)
                mn = fminf(mn, __shfl_xor_sync(0xffffffffu, mn, o));
            unsigned bal = __ballot_sync(0xffffffffu, cur == mn);
            if (lane == (__ffs(bal) - 1)) cur = FINF;
            tau = mn;
        }
        const float Tskip = tau + margin;
        const float Tq = Tskip + 8.0f;

        float um0 = fminf(rm[2 * lane], rm[2 * lane + 1]);          // units 0..31
        float um1 = fminf(rm[64 + 2 * lane], rm[64 + 2 * lane + 1]); // units 32..63

        const uint4* rowp = (const uint4*)(g_approxh + (size_t)q * (M_COLS / 2));
        int* cand = g_cand + (size_t)q * CAP;
        int cnt = 0;
        for (int u = 0; u < 64; ++u) {
            float umin = __shfl_sync(0xffffffffu, (u < 32) ? um0 : um1, u & 31);
            if (umin > Tskip) continue;            // warp-uniform skip
            uint4 v = rowp[u * 32 + lane];
            float2 f0 = unpack_bf16(v.x), f1 = unpack_bf16(v.y);
            float2 f2 = unpack_bf16(v.z), f3 = unpack_bf16(v.w);
            float f[8] = {f0.x, f0.y, f1.x, f1.y, f2.x, f2.y, f3.x, f3.y};
            #pragma unroll
            for (int j = 0; j < 8; ++j) {
                bool p = (f[j] <= Tq);
                unsigned msk = __ballot_sync(0xffffffffu, p);
                if (p) {
                    int off = cnt + __popc(msk & ((1u << lane) - 1u));
                    if (off < CAP) cand[off] = u * 256 + lane * 8 + j;
                }
                cnt += __popc(msk);
            }
        }
        if (lane == 0) g_ccnt[q] = cnt < CAP ? cnt : CAP;
    }
}

// ---------------------------------------------------------------------------
// Exact rescore + select (FROZEN chain + FROZEN epilogue + stable u64 key).
// ---------------------------------------------------------------------------
__global__ __launch_bounds__(64)
void rescore_kernel(const float* __restrict__ x, const float* __restrict__ loc,
                    float* __restrict__ out) {
    __shared__ unsigned long long keys[CAP];
    const int q = blockIdx.x;
    const int tid = threadIdx.x;
    const int cnt = g_ccnt[q];

    const float4* xr = (const float4*)(x + (size_t)q * D_DIM);
    const float x2 = g_x2[q], sx = g_sx[q];

    for (int t = tid; t < cnt; t += 64) {
        int m = g_cand[(size_t)q * CAP + t];
        const float4* wr = (const float4*)(g_wT + (size_t)m * D_DIM);
        float acc = 0.f;
        for (int i = 0; i < D_DIM / 4; ++i) {   // single ascending FMA chain
            float4 a = xr[i], b = wr[i];
            acc = fmaf(a.x, b.x, acc);
            acc = fmaf(a.y, b.y, acc);
            acc = fmaf(a.z, b.z, acc);
            acc = fmaf(a.w, b.w, acc);
        }
        float t1 = __fsub_rn(x2, __fmul_rn(2.0f, acc));
        t1 = __fadd_rn(t1, g_w2[m]);
        float ds = __fsub_rn(sx, g_sw[m]);
        t1 = __fadd_rn(t1, __fmul_rn(C1, ds));
        t1 = __fadd_rn(t1, C2);
        float dist = sqrtf(fmaxf(t1, 0.0f));
        keys[t] = ((unsigned long long)__float_as_uint(dist) << 32) | (unsigned)m;
    }
    __syncthreads();

    if (tid < 32) {
        const int lane = tid;
        #pragma unroll 1
        for (int r = 0; r < N_BMU; ++r) {
            unsigned long long lk = MAXKEY;
            int la = -1;
            for (int idx = lane; idx < cnt; idx += 32) {
                unsigned long long k = keys[idx];
                if (k < lk) { lk = k; la = idx; }
            }
            unsigned long long best = lk;
            #pragma unroll
            for (int o = 16; o; o >>= 1) {
                unsigned long long other = __shfl_xor_sync(0xffffffffu, best, o);
                if (other < best) best = other;
            }
            if (lk == best && la >= 0) keys[la] = MAXKEY;
            if (lane == r) {
                int m = (int)(best & 0xffffffffULL);
                out[((size_t)r * B_ROWS + q) * 2 + 0] = loc[m * 2 + 0];
                out[((size_t)r * B_ROWS + q) * 2 + 1] = loc[m * 2 + 1];
            }
            __syncwarp();
        }
    }
}

__global__ void zero_tail_kernel(float* out, int start, int n) {
    int i = blockIdx.x * blockDim.x + threadIdx.x;
    if (i < n) out[start + i] = 0.0f;
}

extern "C" void kernel_launch(void* const* d_in, const int* in_sizes, int n_in,
                              void* d_out, int out_size) {
    const float* x   = (const float*)d_in[0];
    const float* w   = (const float*)d_in[1];
    const float* loc = (const float*)d_in[2];
    float* out = (float*)d_out;

    cudaFuncSetAttribute(prune_gemm_kernel,
                         cudaFuncAttributeMaxDynamicSharedMemorySize, SMEM_GEMM);

    wstats_kernel<<<M_COLS / 256, 256>>>(w);
    xstats_kernel<<<B_ROWS / 8, 256>>>(x);
    convert_x_kernel<<<(B_ROWS / 16) * (D_DIM / 16) * 32 / 256, 256>>>(x);
    convert_w_kernel<<<(M_COLS / 8) * (D_DIM / 16) * 32 / 256, 256>>>(w);
    transpose_w_kernel<<<dim3(M_COLS / 32, D_DIM / 32), dim3(32, 8)>>>(w);
    prune_gemm_kernel<<<dim3(M_COLS / 128, B_ROWS / 128), 256, SMEM_GEMM>>>();
    rescore_kernel<<<B_ROWS, 64>>>(x, loc, out);

    const int main_elems = N_BMU * B_ROWS * 2;
    if (out_size > main_elems) {
        int tail = out_size - main_elems;
        zero_tail_kernel<<<(tail + 255) / 256, 256>>>(out, main_elems, tail);
    }
}

// round 15
// speedup vs baseline: 1.6413x; 1.6413x over previous
#include <cuda_runtime.h>
#include <cuda_bf16.h>
#include <cstdint>

#define B_ROWS 4096
#define M_COLS 16384
#define D_DIM  512
#define N_BMU  16
#define CAP    256

#define C1 ((float)(2.0 * 1e-6))
#define C2 ((float)(512.0 * (1e-6 * 1e-6)))
#define FINF __int_as_float(0x7f800000)
#define MAXKEY 0xFFFFFFFFFFFFFFFFull

#define NBLK (M_COLS / 128)      // 128 rowmin blocks per row
#define NSTG (D_DIM / 32)        // 16 k-stages
#define SMEM_GEMM 65536          // 4 stages x (8KB A + 8KB B)

// prep job block ranges (all 256-thread blocks)
#define PB_WSTATS 64
#define PB_XSTATS (PB_WSTATS + 512)
#define PB_CVTX   (PB_XSTATS + 1024)
#define PB_CVTW   (PB_CVTX + 8192)
#define PB_TRANS  (PB_CVTW + 8192)   // total 17984

// Scratch (no cudaMalloc allowed)
__device__ unsigned g_approxh[(size_t)B_ROWS * M_COLS / 2];   // bf16x2, 128MB
__device__ float g_rowmin[(size_t)B_ROWS * NBLK];
__device__ float g_w2[M_COLS];
__device__ float g_sw[M_COLS];
__device__ float g_x2[B_ROWS];
__device__ float g_sx[B_ROWS];
__device__ float g_wT[(size_t)M_COLS * D_DIM];
__device__ uint4 g_xfrag[(B_ROWS / 16) * (D_DIM / 16) * 32];
__device__ uint2 g_wfrag[(M_COLS / 8) * (D_DIM / 16) * 32];
__device__ int   g_maxx2_bits;
__device__ int   g_maxw2_bits;

__device__ __forceinline__ unsigned smem_u32(const void* p) {
    return (unsigned)__cvta_generic_to_shared(p);
}
#define CP_ASYNC16(dst, src) \
    asm volatile("cp.async.cg.shared.global [%0], [%1], 16;\n" :: "r"(dst), "l"(src))
#define CP_COMMIT() asm volatile("cp.async.commit_group;\n" ::)
#define CP_WAIT(n)  asm volatile("cp.async.wait_group %0;\n" :: "n"(n))

__device__ __forceinline__ unsigned pack_bf16(float lo, float hi) {
    __nv_bfloat162 h = __floats2bfloat162_rn(lo, hi);
    return *reinterpret_cast<unsigned*>(&h);
}
__device__ __forceinline__ float2 unpack_bf16(unsigned u) {
    __nv_bfloat162 h = *reinterpret_cast<__nv_bfloat162*>(&u);
    return __bfloat1622float2(h);
}
__device__ __forceinline__ void mma_bf16(float c[4], unsigned a0, unsigned a1,
                                         unsigned a2, unsigned a3,
                                         unsigned b0, unsigned b1) {
    asm volatile(
        "mma.sync.aligned.m16n8k16.row.col.f32.bf16.bf16.f32 "
        "{%0,%1,%2,%3}, {%4,%5,%6,%7}, {%8,%9}, {%0,%1,%2,%3};"
        : "+f"(c[0]), "+f"(c[1]), "+f"(c[2]), "+f"(c[3])
        : "r"(a0), "r"(a1), "r"(a2), "r"(a3), "r"(b0), "r"(b1));
}

// ---------------------------------------------------------------------------
// MERGED prep kernel: 5 independent jobs dispatched by blockIdx range.
// Each job's logic is byte-identical to its R12 standalone kernel.
// ---------------------------------------------------------------------------
__global__ __launch_bounds__(256)
void prep_kernel(const float* __restrict__ x, const float* __restrict__ w) {
    __shared__ float tile[32][33];
    const int blk = blockIdx.x;
    const int tid = threadIdx.x;

    if (blk < PB_WSTATS) {
        // ---- wstats (FROZEN): fp64 accumulation of fp32-rounded squares ----
        int m = blk * 256 + tid;
        double w2 = 0.0, sw = 0.0;
        for (int d = 0; d < D_DIM; ++d) {
            float v = w[(size_t)d * M_COLS + m];
            w2 += (double)__fmul_rn(v, v);
            sw += (double)v;
        }
        float w2f = (float)w2;
        g_w2[m] = w2f;
        g_sw[m] = (float)sw;
        atomicMax(&g_maxw2_bits, __float_as_int(w2f));
    } else if (blk < PB_XSTATS) {
        // ---- xstats (FROZEN): fp64 per-row, one warp per row ----
        const int row = (blk - PB_WSTATS) * 8 + (tid >> 5);
        const int lane = tid & 31;
        const float* xr = x + (size_t)row * D_DIM;
        double p2 = 0.0, p1 = 0.0;
        for (int i = lane; i < D_DIM; i += 32) {
            float v = xr[i];
            p2 += (double)__fmul_rn(v, v);
            p1 += (double)v;
        }
        #pragma unroll
        for (int off = 16; off; off >>= 1) {
            p2 += __shfl_xor_sync(0xffffffffu, p2, off);
            p1 += __shfl_xor_sync(0xffffffffu, p1, off);
        }
        if (lane == 0) {
            float x2f = (float)p2;
            g_x2[row] = x2f;
            g_sx[row] = (float)p1;
            atomicMax(&g_maxx2_bits, __float_as_int(x2f));
        }
    } else if (blk < PB_CVTX) {
        // ---- convert_x (fragment layout verified in R9) ----
        int idx = (blk - PB_XSTATS) * 256 + tid;
        int lane = idx & 31;
        int kt = (idx >> 5) % (D_DIM / 16);
        int mt = (idx >> 5) / (D_DIM / 16);
        int r = mt * 16 + (lane >> 2);
        int c = kt * 16 + (lane & 3) * 2;
        const float* base = x + (size_t)r * D_DIM + c;
        uint4 o;
        o.x = pack_bf16(base[0], base[1]);
        o.y = pack_bf16(base[8 * D_DIM], base[8 * D_DIM + 1]);
        o.z = pack_bf16(base[8], base[9]);
        o.w = pack_bf16(base[8 * D_DIM + 8], base[8 * D_DIM + 9]);
        g_xfrag[idx] = o;
    } else if (blk < PB_CVTW) {
        // ---- convert_w (fragment layout verified in R9) ----
        int idx = (blk - PB_CVTX) * 256 + tid;
        int lane = idx & 31;
        int kt = (idx >> 5) % (D_DIM / 16);
        int nt = (idx >> 5) / (D_DIM / 16);
        int k = kt * 16 + (lane & 3) * 2;
        int n = nt * 8 + (lane >> 2);
        const float* base = w + (size_t)k * M_COLS + n;
        uint2 o;
        o.x = pack_bf16(base[0], base[M_COLS]);
        o.y = pack_bf16(base[8 * (size_t)M_COLS], base[9 * (size_t)M_COLS]);
        g_wfrag[idx] = o;
    } else {
        // ---- transpose w -> wT[m][d] ----
        int b = blk - PB_CVTW;
        int bx = b % 512, by = b / 512;
        int tx = tid & 31, ty = tid >> 5;
        #pragma unroll
        for (int i = 0; i < 4; ++i)
            tile[ty + i * 8][tx] =
                w[(size_t)(by * 32 + ty + i * 8) * M_COLS + bx * 32 + tx];
        __syncthreads();
        #pragma unroll
        for (int i = 0; i < 4; ++i)
            g_wT[(size_t)(bx * 32 + ty + i * 8) * D_DIM + by * 32 + tx] =
                tile[tx][ty + i * 8];
    }
}

// ---------------------------------------------------------------------------
// Prune GEMM (R12, byte-identical): bf16 mma.sync, CTA 128x128, warp 64x32,
// 4-stage cp.async pipeline, bf16 staged coalesced stores, fp32 rowmins.
// ---------------------------------------------------------------------------
__global__ __launch_bounds__(256, 2)
void prune_gemm_kernel() {
    extern __shared__ char smem[];
    uint4* As = (uint4*)smem;                     // [4][512]
    uint2* Bs = (uint2*)(smem + 32768);           // [4][1024]

    const int tid = threadIdx.x;
    const int lane = tid & 31;
    const int wid = tid >> 5;
    const int wm = wid >> 2;          // 0..1
    const int wn = wid & 3;           // 0..3
    const int ntile = blockIdx.x, mtile = blockIdx.y;
    const int mtBase = mtile * 8;
    const int ntBase = ntile * 16;

    float c[4][4][4];
    #pragma unroll
    for (int i = 0; i < 4; ++i)
        #pragma unroll
        for (int j = 0; j < 4; ++j)
            #pragma unroll
            for (int r = 0; r < 4; ++r) c[i][j][r] = 0.f;

    auto issue = [&](int s) {
        const int buf = s & 3;
        #pragma unroll
        for (int r = 0; r < 2; ++r) {
            int ch = tid + r * 256;
            int mt = ch >> 6, kt = (ch >> 5) & 1, ln = ch & 31;
            const uint4* src = g_xfrag +
                ((size_t)(mtBase + mt) * (D_DIM / 16) + s * 2 + kt) * 32 + ln;
            CP_ASYNC16(smem_u32(&As[buf * 512 + ch]), src);
        }
        #pragma unroll
        for (int r = 0; r < 2; ++r) {
            int cb = tid + r * 256;
            int nt = cb >> 5, kt = (cb >> 4) & 1, lp = cb & 15;
            const uint2* src = g_wfrag +
                ((size_t)(ntBase + nt) * (D_DIM / 16) + s * 2 + kt) * 32 + lp * 2;
            CP_ASYNC16(smem_u32(&Bs[buf * 1024 + ((nt * 2 + kt) * 32 + lp * 2)]), src);
        }
        CP_COMMIT();
    };

    issue(0); issue(1); issue(2);

    for (int s = 0; s < NSTG; ++s) {
        if (s <= 13)      { CP_WAIT(2); }
        else if (s == 14) { CP_WAIT(1); }
        else              { CP_WAIT(0); }
        __syncthreads();
        if (s + 3 < NSTG) issue(s + 3);

        const int buf = s & 3;
        #pragma unroll
        for (int kt = 0; kt < 2; ++kt) {
            uint4 a[4];
            #pragma unroll
            for (int i = 0; i < 4; ++i)
                a[i] = As[buf * 512 + ((wm * 4 + i) * 2 + kt) * 32 + lane];
            uint2 b[4];
            #pragma unroll
            for (int j = 0; j < 4; ++j)
                b[j] = Bs[buf * 1024 + ((wn * 4 + j) * 2 + kt) * 32 + lane];
            #pragma unroll
            for (int i = 0; i < 4; ++i)
                #pragma unroll
                for (int j = 0; j < 4; ++j)
                    mma_bf16(c[i][j], a[i].x, a[i].y, a[i].z, a[i].w, b[j].x, b[j].y);
        }
    }
    __syncthreads();

    unsigned* st = (unsigned*)smem;             // [128][68] u32 (bf16x2)
    float* srm = (float*)(smem + 128 * 68 * 4); // [128]
    if (tid < 128) srm[tid] = FINF;
    __syncthreads();

    #pragma unroll
    for (int i = 0; i < 4; ++i) {
        int rl = wm * 64 + i * 16 + (lane >> 2);
        int gr = mtile * 128 + rl;
        float x2a = g_x2[gr], x2b = g_x2[gr + 8];
        float rmin0 = FINF, rmin1 = FINF;
        #pragma unroll
        for (int j = 0; j < 4; ++j) {
            int gc = ntile * 128 + wn * 32 + j * 8 + (lane & 3) * 2;
            float w2a = g_w2[gc], w2b = g_w2[gc + 1];
            float s0 = x2a + w2a - 2.f * c[i][j][0];
            float s1 = x2a + w2b - 2.f * c[i][j][1];
            float s2 = x2b + w2a - 2.f * c[i][j][2];
            float s3 = x2b + w2b - 2.f * c[i][j][3];
            int stcol = wn * 16 + j * 4 + (lane & 3);
            st[rl * 68 + stcol]       = pack_bf16(s0, s1);
            st[(rl + 8) * 68 + stcol] = pack_bf16(s2, s3);
            rmin0 = fminf(rmin0, fminf(s0, s1));
            rmin1 = fminf(rmin1, fminf(s2, s3));
        }
        rmin0 = fminf(rmin0, __shfl_xor_sync(0xffffffffu, rmin0, 1));
        rmin0 = fminf(rmin0, __shfl_xor_sync(0xffffffffu, rmin0, 2));
        rmin1 = fminf(rmin1, __shfl_xor_sync(0xffffffffu, rmin1, 1));
        rmin1 = fminf(rmin1, __shfl_xor_sync(0xffffffffu, rmin1, 2));
        if ((lane & 3) == 0) {
            atomicMin((int*)&srm[rl],     __float_as_int(fmaxf(rmin0, 0.f)));
            atomicMin((int*)&srm[rl + 8], __float_as_int(fmaxf(rmin1, 0.f)));
        }
    }
    __syncthreads();

    #pragma unroll
    for (int p = 0; p < 8; ++p) {
        int rl = p * 16 + (tid >> 4);
        uint4 v = *(uint4*)&st[rl * 68 + (tid & 15) * 4];
        *(uint4*)(g_approxh + (size_t)(mtile * 128 + rl) * (M_COLS / 2) +
                  ntile * 64 + (tid & 15) * 4) = v;
    }
    if (tid < 128)
        g_rowmin[(size_t)(mtile * 128 + tid) * NBLK + ntile] = srm[tid];
}

// ---------------------------------------------------------------------------
// FUSED collect + exact rescore, one 64-thread block per query row.
// Warp 0: R12 collect logic (R14-verified shfl unit-min variant) -> smem.
// Both warps: FROZEN ascending fp32 FMA chain + FROZEN epilogue.
// Warp 0: stable u64-key extract-min selection (== jnp.argsort order).
// ---------------------------------------------------------------------------
__global__ __launch_bounds__(64)
void collect_rescore_kernel(const float* __restrict__ x,
                            const float* __restrict__ loc,
                            float* __restrict__ out) {
    __shared__ int s_cand[CAP];
    __shared__ unsigned long long keys[CAP];
    __shared__ int s_cnt;
    const int q = blockIdx.x;
    const int tid = threadIdx.x;
    const int lane = tid & 31;

    if (tid < 32) {
        float mx = __int_as_float(g_maxx2_bits);
        float mw = __int_as_float(g_maxw2_bits);
        float margin = 0.017f * sqrtf(mx * mw) + 0.25f;

        const float* rm = g_rowmin + (size_t)q * NBLK;
        float lmin = fminf(fminf(rm[lane], rm[lane + 32]),
                           fminf(rm[lane + 64], rm[lane + 96]));
        float cur = lmin, tau = FINF;
        #pragma unroll
        for (int r = 0; r < N_BMU; ++r) {
            float mn = cur;
            #pragma unroll
            for (int o = 16; o; o >>= 1)
                mn = fminf(mn, __shfl_xor_sync(0xffffffffu, mn, o));
            unsigned bal = __ballot_sync(0xffffffffu, cur == mn);
            if (lane == (__ffs(bal) - 1)) cur = FINF;
            tau = mn;
        }
        const float Tskip = tau + margin;
        const float Tq = Tskip + 8.0f;

        float um0 = fminf(rm[2 * lane], rm[2 * lane + 1]);           // units 0..31
        float um1 = fminf(rm[64 + 2 * lane], rm[64 + 2 * lane + 1]); // units 32..63

        const uint4* rowp = (const uint4*)(g_approxh + (size_t)q * (M_COLS / 2));
        int cnt = 0;
        for (int u = 0; u < 64; ++u) {
            float umin = __shfl_sync(0xffffffffu, (u < 32) ? um0 : um1, u & 31);
            if (umin > Tskip) continue;            // warp-uniform skip
            uint4 v = rowp[u * 32 + lane];
            float2 f0 = unpack_bf16(v.x), f1 = unpack_bf16(v.y);
            float2 f2 = unpack_bf16(v.z), f3 = unpack_bf16(v.w);
            float f[8] = {f0.x, f0.y, f1.x, f1.y, f2.x, f2.y, f3.x, f3.y};
            #pragma unroll
            for (int j = 0; j < 8; ++j) {
                bool p = (f[j] <= Tq);
                unsigned msk = __ballot_sync(0xffffffffu, p);
                if (p) {
                    int off = cnt + __popc(msk & ((1u << lane) - 1u));
                    if (off < CAP) s_cand[off] = u * 256 + lane * 8 + j;
                }
                cnt += __popc(msk);
            }
        }
        if (lane == 0) s_cnt = cnt < CAP ? cnt : CAP;
    }
    __syncthreads();
    const int cnt = s_cnt;

    const float4* xr = (const float4*)(x + (size_t)q * D_DIM);
    const float x2 = g_x2[q], sx = g_sx[q];

    for (int t = tid; t < cnt; t += 64) {
        int m = s_cand[t];
        const float4* wr = (const float4*)(g_wT + (size_t)m * D_DIM);
        float acc = 0.f;
        for (int i = 0; i < D_DIM / 4; ++i) {   // FROZEN ascending FMA chain
            float4 a = xr[i], b = wr[i];
            acc = fmaf(a.x, b.x, acc);
            acc = fmaf(a.y, b.y, acc);
            acc = fmaf(a.z, b.z, acc);
            acc = fmaf(a.w, b.w, acc);
        }
        float t1 = __fsub_rn(x2, __fmul_rn(2.0f, acc));   // FROZEN epilogue
        t1 = __fadd_rn(t1, g_w2[m]);
        float ds = __fsub_rn(sx, g_sw[m]);
        t1 = __fadd_rn(t1, __fmul_rn(C1, ds));
        t1 = __fadd_rn(t1, C2);
        float dist = sqrtf(fmaxf(t1, 0.0f));
        keys[t] = ((unsigned long long)__float_as_uint(dist) << 32) | (unsigned)m;
    }
    __syncthreads();

    if (tid < 32) {
        #pragma unroll 1
        for (int r = 0; r < N_BMU; ++r) {
            unsigned long long lk = MAXKEY;
            int la = -1;
            for (int idx = lane; idx < cnt; idx += 32) {
                unsigned long long k = keys[idx];
                if (k < lk) { lk = k; la = idx; }
            }
            unsigned long long best = lk;
            #pragma unroll
            for (int o = 16; o; o >>= 1) {
                unsigned long long other = __shfl_xor_sync(0xffffffffu, best, o);
                if (other < best) best = other;
            }
            if (lk == best && la >= 0) keys[la] = MAXKEY;
            if (lane == r) {
                int m = (int)(best & 0xffffffffULL);
                out[((size_t)r * B_ROWS + q) * 2 + 0] = loc[m * 2 + 0];
                out[((size_t)r * B_ROWS + q) * 2 + 1] = loc[m * 2 + 1];
            }
            __syncwarp();
        }
    }
}

__global__ void zero_tail_kernel(float* out, int start, int n) {
    int i = blockIdx.x * blockDim.x + threadIdx.x;
    if (i < n) out[start + i] = 0.0f;
}

extern "C" void kernel_launch(void* const* d_in, const int* in_sizes, int n_in,
                              void* d_out, int out_size) {
    const float* x   = (const float*)d_in[0];
    const float* w   = (const float*)d_in[1];
    const float* loc = (const float*)d_in[2];
    float* out = (float*)d_out;

    cudaFuncSetAttribute(prune_gemm_kernel,
                         cudaFuncAttributeMaxDynamicSharedMemorySize, SMEM_GEMM);

    prep_kernel<<<PB_TRANS, 256>>>(x, w);
    prune_gemm_kernel<<<dim3(M_COLS / 128, B_ROWS / 128), 256, SMEM_GEMM>>>();
    collect_rescore_kernel<<<B_ROWS, 64>>>(x, loc, out);

    const int main_elems = N_BMU * B_ROWS * 2;
    if (out_size > main_elems) {
        int tail = out_size - main_elems;
        zero_tail_kernel<<<(tail + 255) / 256, 256>>>(out, main_elems, tail);
    }
}

// round 16
// speedup vs baseline: 1.6592x; 1.0109x over previous
#include <cuda_runtime.h>
#include <cuda_bf16.h>
#include <cstdint>

#define B_ROWS 4096
#define M_COLS 16384
#define D_DIM  512
#define N_BMU  16
#define CAP    256

#define C1 ((float)(2.0 * 1e-6))
#define C2 ((float)(512.0 * (1e-6 * 1e-6)))
#define FINF __int_as_float(0x7f800000)
#define MAXKEY 0xFFFFFFFFFFFFFFFFull

#define NBLK (M_COLS / 128)      // 128 rowmin blocks per row
#define NSTG (D_DIM / 32)        // 16 k-stages
#define SMEM_GEMM 65536          // 4 stages x (8KB A + 8KB B)

// prep job block ranges (all 256-thread blocks)
#define PB_WSTATS 64
#define PB_XSTATS (PB_WSTATS + 512)
#define PB_CVTX   (PB_XSTATS + 1024)
#define PB_WTILE  (PB_CVTX + 8192)    // fused convert_w + transpose (32x32 tiles)
#define PB_TOTAL  PB_WTILE            // 16960... (PB_CVTX + 8192)

// Scratch (no cudaMalloc allowed)
__device__ unsigned g_approxh[(size_t)B_ROWS * M_COLS / 2];   // bf16x2, 128MB
__device__ float g_rowmin[(size_t)B_ROWS * NBLK];
__device__ float g_w2[M_COLS];
__device__ float g_sw[M_COLS];
__device__ float g_x2[B_ROWS];
__device__ float g_sx[B_ROWS];
__device__ float g_wT[(size_t)M_COLS * D_DIM];
__device__ uint4 g_xfrag[(B_ROWS / 16) * (D_DIM / 16) * 32];
__device__ uint2 g_wfrag[(M_COLS / 8) * (D_DIM / 16) * 32];
__device__ int   g_maxx2_bits;
__device__ int   g_maxw2_bits;

__device__ __forceinline__ unsigned smem_u32(const void* p) {
    return (unsigned)__cvta_generic_to_shared(p);
}
#define CP_ASYNC16(dst, src) \
    asm volatile("cp.async.cg.shared.global [%0], [%1], 16;\n" :: "r"(dst), "l"(src))
#define CP_COMMIT() asm volatile("cp.async.commit_group;\n" ::)
#define CP_WAIT(n)  asm volatile("cp.async.wait_group %0;\n" :: "n"(n))

__device__ __forceinline__ unsigned pack_bf16(float lo, float hi) {
    __nv_bfloat162 h = __floats2bfloat162_rn(lo, hi);
    return *reinterpret_cast<unsigned*>(&h);
}
__device__ __forceinline__ float2 unpack_bf16(unsigned u) {
    __nv_bfloat162 h = *reinterpret_cast<__nv_bfloat162*>(&u);
    return __bfloat1622float2(h);
}
__device__ __forceinline__ void mma_bf16(float c[4], unsigned a0, unsigned a1,
                                         unsigned a2, unsigned a3,
                                         unsigned b0, unsigned b1) {
    asm volatile(
        "mma.sync.aligned.m16n8k16.row.col.f32.bf16.bf16.f32 "
        "{%0,%1,%2,%3}, {%4,%5,%6,%7}, {%8,%9}, {%0,%1,%2,%3};"
        : "+f"(c[0]), "+f"(c[1]), "+f"(c[2]), "+f"(c[3])
        : "r"(a0), "r"(a1), "r"(a2), "r"(a3), "r"(b0), "r"(b1));
}

// ---------------------------------------------------------------------------
// MERGED prep kernel. wstats/xstats/convert_x byte-identical to R15.
// NEW: convert_w + transpose fused into one 32x32-tile job (w read ONCE).
// ---------------------------------------------------------------------------
__global__ __launch_bounds__(256)
void prep_kernel(const float* __restrict__ x, const float* __restrict__ w) {
    __shared__ float tile[32][33];
    const int blk = blockIdx.x;
    const int tid = threadIdx.x;

    if (blk < PB_WSTATS) {
        // ---- wstats (FROZEN): fp64 accumulation of fp32-rounded squares ----
        int m = blk * 256 + tid;
        double w2 = 0.0, sw = 0.0;
        for (int d = 0; d < D_DIM; ++d) {
            float v = w[(size_t)d * M_COLS + m];
            w2 += (double)__fmul_rn(v, v);
            sw += (double)v;
        }
        float w2f = (float)w2;
        g_w2[m] = w2f;
        g_sw[m] = (float)sw;
        atomicMax(&g_maxw2_bits, __float_as_int(w2f));
    } else if (blk < PB_XSTATS) {
        // ---- xstats (FROZEN): fp64 per-row, one warp per row ----
        const int row = (blk - PB_WSTATS) * 8 + (tid >> 5);
        const int lane = tid & 31;
        const float* xr = x + (size_t)row * D_DIM;
        double p2 = 0.0, p1 = 0.0;
        for (int i = lane; i < D_DIM; i += 32) {
            float v = xr[i];
            p2 += (double)__fmul_rn(v, v);
            p1 += (double)v;
        }
        #pragma unroll
        for (int off = 16; off; off >>= 1) {
            p2 += __shfl_xor_sync(0xffffffffu, p2, off);
            p1 += __shfl_xor_sync(0xffffffffu, p1, off);
        }
        if (lane == 0) {
            float x2f = (float)p2;
            g_x2[row] = x2f;
            g_sx[row] = (float)p1;
            atomicMax(&g_maxx2_bits, __float_as_int(x2f));
        }
    } else if (blk < PB_CVTX) {
        // ---- convert_x (fragment layout verified in R9) ----
        int idx = (blk - PB_XSTATS) * 256 + tid;
        int lane = idx & 31;
        int kt = (idx >> 5) % (D_DIM / 16);
        int mt = (idx >> 5) / (D_DIM / 16);
        int r = mt * 16 + (lane >> 2);
        int c = kt * 16 + (lane & 3) * 2;
        const float* base = x + (size_t)r * D_DIM + c;
        uint4 o;
        o.x = pack_bf16(base[0], base[1]);
        o.y = pack_bf16(base[8 * D_DIM], base[8 * D_DIM + 1]);
        o.z = pack_bf16(base[8], base[9]);
        o.w = pack_bf16(base[8 * D_DIM + 8], base[8 * D_DIM + 9]);
        g_xfrag[idx] = o;
    } else {
        // ---- FUSED wT transpose + convert_w from one 32x32 tile of w ----
        int b = blk - PB_CVTX;
        int bx = b % 512, by = b / 512;     // bx: n-block(32), by: k-block(32)
        int tx = tid & 31, ty = tid >> 5;   // loader: tx = n-local, ty-phase = k
        const int n0 = bx * 32, k0 = by * 32;
        #pragma unroll
        for (int i = 0; i < 4; ++i)
            tile[ty + i * 8][tx] = w[(size_t)(k0 + ty + i * 8) * M_COLS + n0 + tx];
        __syncthreads();
        // transpose store: wT[n][k]
        #pragma unroll
        for (int i = 0; i < 4; ++i)
            g_wT[(size_t)(n0 + ty + i * 8) * D_DIM + k0 + tx] = tile[tx][ty + i * 8];
        // frag store: 8 frag-groups (4 nt_local x 2 kt_local) x 32 lanes
        {
            const int g = tid >> 5;                // 0..7
            const int lane = tid & 31;
            const int ntl = g & 3, ktl = g >> 2;   // nt-local, kt-local
            const int kl = ktl * 16 + (lane & 3) * 2;
            const int nl = ntl * 8 + (lane >> 2);
            uint2 o;
            o.x = pack_bf16(tile[kl][nl], tile[kl + 1][nl]);
            o.y = pack_bf16(tile[kl + 8][nl], tile[kl + 9][nl]);
            const int nt = (n0 >> 3) + ntl;
            const int kt = (k0 >> 4) + ktl;
            g_wfrag[((size_t)nt * (D_DIM / 16) + kt) * 32 + lane] = o;
        }
    }
}

// ---------------------------------------------------------------------------
// Prune GEMM (R12, byte-identical): bf16 mma.sync, CTA 128x128, warp 64x32,
// 4-stage cp.async pipeline, bf16 staged coalesced stores, fp32 rowmins.
// ---------------------------------------------------------------------------
__global__ __launch_bounds__(256, 2)
void prune_gemm_kernel() {
    extern __shared__ char smem[];
    uint4* As = (uint4*)smem;                     // [4][512]
    uint2* Bs = (uint2*)(smem + 32768);           // [4][1024]

    const int tid = threadIdx.x;
    const int lane = tid & 31;
    const int wid = tid >> 5;
    const int wm = wid >> 2;          // 0..1
    const int wn = wid & 3;           // 0..3
    const int ntile = blockIdx.x, mtile = blockIdx.y;
    const int mtBase = mtile * 8;
    const int ntBase = ntile * 16;

    float c[4][4][4];
    #pragma unroll
    for (int i = 0; i < 4; ++i)
        #pragma unroll
        for (int j = 0; j < 4; ++j)
            #pragma unroll
            for (int r = 0; r < 4; ++r) c[i][j][r] = 0.f;

    auto issue = [&](int s) {
        const int buf = s & 3;
        #pragma unroll
        for (int r = 0; r < 2; ++r) {
            int ch = tid + r * 256;
            int mt = ch >> 6, kt = (ch >> 5) & 1, ln = ch & 31;
            const uint4* src = g_xfrag +
                ((size_t)(mtBase + mt) * (D_DIM / 16) + s * 2 + kt) * 32 + ln;
            CP_ASYNC16(smem_u32(&As[buf * 512 + ch]), src);
        }
        #pragma unroll
        for (int r = 0; r < 2; ++r) {
            int cb = tid + r * 256;
            int nt = cb >> 5, kt = (cb >> 4) & 1, lp = cb & 15;
            const uint2* src = g_wfrag +
                ((size_t)(ntBase + nt) * (D_DIM / 16) + s * 2 + kt) * 32 + lp * 2;
            CP_ASYNC16(smem_u32(&Bs[buf * 1024 + ((nt * 2 + kt) * 32 + lp * 2)]), src);
        }
        CP_COMMIT();
    };

    issue(0); issue(1); issue(2);

    for (int s = 0; s < NSTG; ++s) {
        if (s <= 13)      { CP_WAIT(2); }
        else if (s == 14) { CP_WAIT(1); }
        else              { CP_WAIT(0); }
        __syncthreads();
        if (s + 3 < NSTG) issue(s + 3);

        const int buf = s & 3;
        #pragma unroll
        for (int kt = 0; kt < 2; ++kt) {
            uint4 a[4];
            #pragma unroll
            for (int i = 0; i < 4; ++i)
                a[i] = As[buf * 512 + ((wm * 4 + i) * 2 + kt) * 32 + lane];
            uint2 b[4];
            #pragma unroll
            for (int j = 0; j < 4; ++j)
                b[j] = Bs[buf * 1024 + ((wn * 4 + j) * 2 + kt) * 32 + lane];
            #pragma unroll
            for (int i = 0; i < 4; ++i)
                #pragma unroll
                for (int j = 0; j < 4; ++j)
                    mma_bf16(c[i][j], a[i].x, a[i].y, a[i].z, a[i].w, b[j].x, b[j].y);
        }
    }
    __syncthreads();

    unsigned* st = (unsigned*)smem;             // [128][68] u32 (bf16x2)
    float* srm = (float*)(smem + 128 * 68 * 4); // [128]
    if (tid < 128) srm[tid] = FINF;
    __syncthreads();

    #pragma unroll
    for (int i = 0; i < 4; ++i) {
        int rl = wm * 64 + i * 16 + (lane >> 2);
        int gr = mtile * 128 + rl;
        float x2a = g_x2[gr], x2b = g_x2[gr + 8];
        float rmin0 = FINF, rmin1 = FINF;
        #pragma unroll
        for (int j = 0; j < 4; ++j) {
            int gc = ntile * 128 + wn * 32 + j * 8 + (lane & 3) * 2;
            float w2a = g_w2[gc], w2b = g_w2[gc + 1];
            float s0 = x2a + w2a - 2.f * c[i][j][0];
            float s1 = x2a + w2b - 2.f * c[i][j][1];
            float s2 = x2b + w2a - 2.f * c[i][j][2];
            float s3 = x2b + w2b - 2.f * c[i][j][3];
            int stcol = wn * 16 + j * 4 + (lane & 3);
            st[rl * 68 + stcol]       = pack_bf16(s0, s1);
            st[(rl + 8) * 68 + stcol] = pack_bf16(s2, s3);
            rmin0 = fminf(rmin0, fminf(s0, s1));
            rmin1 = fminf(rmin1, fminf(s2, s3));
        }
        rmin0 = fminf(rmin0, __shfl_xor_sync(0xffffffffu, rmin0, 1));
        rmin0 = fminf(rmin0, __shfl_xor_sync(0xffffffffu, rmin0, 2));
        rmin1 = fminf(rmin1, __shfl_xor_sync(0xffffffffu, rmin1, 1));
        rmin1 = fminf(rmin1, __shfl_xor_sync(0xffffffffu, rmin1, 2));
        if ((lane & 3) == 0) {
            atomicMin((int*)&srm[rl],     __float_as_int(fmaxf(rmin0, 0.f)));
            atomicMin((int*)&srm[rl + 8], __float_as_int(fmaxf(rmin1, 0.f)));
        }
    }
    __syncthreads();

    #pragma unroll
    for (int p = 0; p < 8; ++p) {
        int rl = p * 16 + (tid >> 4);
        uint4 v = *(uint4*)&st[rl * 68 + (tid & 15) * 4];
        *(uint4*)(g_approxh + (size_t)(mtile * 128 + rl) * (M_COLS / 2) +
                  ntile * 64 + (tid & 15) * 4) = v;
    }
    if (tid < 128)
        g_rowmin[(size_t)(mtile * 128 + tid) * NBLK + ntile] = srm[tid];
}

// ---------------------------------------------------------------------------
// FUSED collect + exact rescore (+ tail zeroing in block 0).
// Quant bound: values tested are <= Tskip; if Tskip <= 2040 their bf16
// storage error <= half-ulp(2048) = 4, else fall back to +8. Superset proof
// unchanged otherwise.
// ---------------------------------------------------------------------------
__global__ __launch_bounds__(64)
void collect_rescore_kernel(const float* __restrict__ x,
                            const float* __restrict__ loc,
                            float* __restrict__ out, int out_size) {
    __shared__ int s_cand[CAP];
    __shared__ unsigned long long keys[CAP];
    __shared__ int s_cnt;
    const int q = blockIdx.x;
    const int tid = threadIdx.x;
    const int lane = tid & 31;

    if (q == 0) {   // tail zeroing (out poisoned by harness)
        const int main_elems = N_BMU * B_ROWS * 2;
        for (int i = main_elems + tid; i < out_size; i += 64) out[i] = 0.0f;
    }

    if (tid < 32) {
        float mx = __int_as_float(g_maxx2_bits);
        float mw = __int_as_float(g_maxw2_bits);
        float margin = 0.017f * sqrtf(mx * mw) + 0.25f;

        const float* rm = g_rowmin + (size_t)q * NBLK;
        float lmin = fminf(fminf(rm[lane], rm[lane + 32]),
                           fminf(rm[lane + 64], rm[lane + 96]));
        float cur = lmin, tau = FINF;
        #pragma unroll
        for (int r = 0; r < N_BMU; ++r) {
            float mn = cur;
            #pragma unroll
            for (int o = 16; o; o >>= 1)
                mn = fminf(mn, __shfl_xor_sync(0xffffffffu, mn, o));
            unsigned bal = __ballot_sync(0xffffffffu, cur == mn);
            if (lane == (__ffs(bal) - 1)) cur = FINF;
            tau = mn;
        }
        const float Tskip = tau + margin;
        const float Tq = Tskip + ((Tskip <= 2040.0f) ? 4.0f : 8.0f);

        float um0 = fminf(rm[2 * lane], rm[2 * lane + 1]);           // units 0..31
        float um1 = fminf(rm[64 + 2 * lane], rm[64 + 2 * lane + 1]); // units 32..63

        const uint4* rowp = (const uint4*)(g_approxh + (size_t)q * (M_COLS / 2));
        int cnt = 0;
        for (int u = 0; u < 64; ++u) {
            float umin = __shfl_sync(0xffffffffu, (u < 32) ? um0 : um1, u & 31);
            if (umin > Tskip) continue;            // warp-uniform skip
            uint4 v = rowp[u * 32 + lane];
            float2 f0 = unpack_bf16(v.x), f1 = unpack_bf16(v.y);
            float2 f2 = unpack_bf16(v.z), f3 = unpack_bf16(v.w);
            float f[8] = {f0.x, f0.y, f1.x, f1.y, f2.x, f2.y, f3.x, f3.y};
            #pragma unroll
            for (int j = 0; j < 8; ++j) {
                bool p = (f[j] <= Tq);
                unsigned msk = __ballot_sync(0xffffffffu, p);
                if (p) {
                    int off = cnt + __popc(msk & ((1u << lane) - 1u));
                    if (off < CAP) s_cand[off] = u * 256 + lane * 8 + j;
                }
                cnt += __popc(msk);
            }
        }
        if (lane == 0) s_cnt = cnt < CAP ? cnt : CAP;
    }
    __syncthreads();
    const int cnt = s_cnt;

    const float4* xr = (const float4*)(x + (size_t)q * D_DIM);
    const float x2 = g_x2[q], sx = g_sx[q];

    for (int t = tid; t < cnt; t += 64) {
        int m = s_cand[t];
        const float4* wr = (const float4*)(g_wT + (size_t)m * D_DIM);
        float acc = 0.f;
        for (int i = 0; i < D_DIM / 4; ++i) {   // FROZEN ascending FMA chain
            float4 a = xr[i], b = wr[i];
            acc = fmaf(a.x, b.x, acc);
            acc = fmaf(a.y, b.y, acc);
            acc = fmaf(a.z, b.z, acc);
            acc = fmaf(a.w, b.w, acc);
        }
        float t1 = __fsub_rn(x2, __fmul_rn(2.0f, acc));   // FROZEN epilogue
        t1 = __fadd_rn(t1, g_w2[m]);
        float ds = __fsub_rn(sx, g_sw[m]);
        t1 = __fadd_rn(t1, __fmul_rn(C1, ds));
        t1 = __fadd_rn(t1, C2);
        float dist = sqrtf(fmaxf(t1, 0.0f));
        keys[t] = ((unsigned long long)__float_as_uint(dist) << 32) | (unsigned)m;
    }
    __syncthreads();

    if (tid < 32) {
        #pragma unroll 1
        for (int r = 0; r < N_BMU; ++r) {
            unsigned long long lk = MAXKEY;
            int la = -1;
            for (int idx = lane; idx < cnt; idx += 32) {
                unsigned long long k = keys[idx];
                if (k < lk) { lk = k; la = idx; }
            }
            unsigned long long best = lk;
            #pragma unroll
            for (int o = 16; o; o >>= 1) {
                unsigned long long other = __shfl_xor_sync(0xffffffffu, best, o);
                if (other < best) best = other;
            }
            if (lk == best && la >= 0) keys[la] = MAXKEY;
            if (lane == r) {
                int m = (int)(best & 0xffffffffULL);
                out[((size_t)r * B_ROWS + q) * 2 + 0] = loc[m * 2 + 0];
                out[((size_t)r * B_ROWS + q) * 2 + 1] = loc[m * 2 + 1];
            }
            __syncwarp();
        }
    }
}

extern "C" void kernel_launch(void* const* d_in, const int* in_sizes, int n_in,
                              void* d_out, int out_size) {
    const float* x   = (const float*)d_in[0];
    const float* w   = (const float*)d_in[1];
    const float* loc = (const float*)d_in[2];
    float* out = (float*)d_out;

    cudaFuncSetAttribute(prune_gemm_kernel,
                         cudaFuncAttributeMaxDynamicSharedMemorySize, SMEM_GEMM);

    prep_kernel<<<PB_WTILE, 256>>>(x, w);
    prune_gemm_kernel<<<dim3(M_COLS / 128, B_ROWS / 128), 256, SMEM_GEMM>>>();
    collect_rescore_kernel<<<B_ROWS, 64>>>(x, loc, out, out_size);
}

// round 17
// speedup vs baseline: 1.9651x; 1.1844x over previous
#include <cuda_runtime.h>
#include <cuda_bf16.h>
#include <cstdint>

#define B_ROWS 4096
#define M_COLS 16384
#define D_DIM  512
#define N_BMU  16
#define CAP    256

#define C1 ((float)(2.0 * 1e-6))
#define C2 ((float)(512.0 * (1e-6 * 1e-6)))
#define FINF __int_as_float(0x7f800000)
#define MAXKEY 0xFFFFFFFFFFFFFFFFull

#define NBLK (M_COLS / 128)      // 128 rowmin blocks per row
#define NSTG (D_DIM / 32)        // 16 k-stages
#define SMEM_GEMM 65536          // 4 stages x (8KB A + 8KB B)

// prep job block ranges (all 256-thread blocks)
#define PB_WSTATS 512                  // tiled wstats: 32 cols/block
#define PB_XSTATS (PB_WSTATS + 512)
#define PB_CVTX   (PB_XSTATS + 1024)
#define PB_WTILE  (PB_CVTX + 8192)     // fused convert_w + transpose

// Scratch (no cudaMalloc allowed)
__device__ unsigned g_approxh[(size_t)B_ROWS * M_COLS / 2];   // bf16x2, 128MB
__device__ float g_rowmin[(size_t)B_ROWS * NBLK];
__device__ float g_w2[M_COLS];
__device__ float g_sw[M_COLS];
__device__ float g_x2[B_ROWS];
__device__ float g_sx[B_ROWS];
__device__ float g_wT[(size_t)M_COLS * D_DIM];
__device__ uint4 g_xfrag[(B_ROWS / 16) * (D_DIM / 16) * 32];
__device__ uint2 g_wfrag[(M_COLS / 8) * (D_DIM / 16) * 32];
__device__ int   g_maxx2_bits;
__device__ int   g_maxw2_bits;

__device__ __forceinline__ unsigned smem_u32(const void* p) {
    return (unsigned)__cvta_generic_to_shared(p);
}
#define CP_ASYNC16(dst, src) \
    asm volatile("cp.async.cg.shared.global [%0], [%1], 16;\n" :: "r"(dst), "l"(src))
#define CP_COMMIT() asm volatile("cp.async.commit_group;\n" ::)
#define CP_WAIT(n)  asm volatile("cp.async.wait_group %0;\n" :: "n"(n))

__device__ __forceinline__ unsigned pack_bf16(float lo, float hi) {
    __nv_bfloat162 h = __floats2bfloat162_rn(lo, hi);
    return *reinterpret_cast<unsigned*>(&h);
}
__device__ __forceinline__ float2 unpack_bf16(unsigned u) {
    __nv_bfloat162 h = *reinterpret_cast<__nv_bfloat162*>(&u);
    return __bfloat1622float2(h);
}
__device__ __forceinline__ void mma_bf16(float c[4], unsigned a0, unsigned a1,
                                         unsigned a2, unsigned a3,
                                         unsigned b0, unsigned b1) {
    asm volatile(
        "mma.sync.aligned.m16n8k16.row.col.f32.bf16.bf16.f32 "
        "{%0,%1,%2,%3}, {%4,%5,%6,%7}, {%8,%9}, {%0,%1,%2,%3};"
        : "+f"(c[0]), "+f"(c[1]), "+f"(c[2]), "+f"(c[3])
        : "r"(a0), "r"(a1), "r"(a2), "r"(a3), "r"(b0), "r"(b1));
}

// ---------------------------------------------------------------------------
// MERGED prep kernel.
// wstats v2: 512 blocks, smem-tiled coalesced, fp64 partials across 256
// threads, fixed-order combine (fp64 reorder only: bitwise-safe vs fp32 round).
// xstats / convert_x / fused wT+convert_w byte-identical to R16.
// ---------------------------------------------------------------------------
__global__ __launch_bounds__(256)
void prep_kernel(const float* __restrict__ x, const float* __restrict__ w) {
    __shared__ float tile[32][33];
    __shared__ double s2d[8][33];
    __shared__ double s1d[8][33];
    const int blk = blockIdx.x;
    const int tid = threadIdx.x;

    if (blk < PB_WSTATS) {
        // ---- wstats v2: 32 columns per block, tiled over 16 k-chunks ----
        const int n0 = blk * 32;
        const int tcol = tid & 31, tseg = tid >> 5;
        double w2 = 0.0, sw = 0.0;
        for (int ch = 0; ch < 16; ++ch) {
            const int k0 = ch * 32;
            #pragma unroll
            for (int i = 0; i < 4; ++i)
                tile[tseg + i * 8][tcol] =
                    w[(size_t)(k0 + tseg + i * 8) * M_COLS + n0 + tcol];
            __syncthreads();
            #pragma unroll
            for (int i = 0; i < 4; ++i) {
                float v = tile[tseg * 4 + i][tcol];
                w2 += (double)__fmul_rn(v, v);   // fp32-rounded square, fp64 sum
                sw += (double)v;
            }
            __syncthreads();
        }
        s2d[tseg][tcol] = w2;
        s1d[tseg][tcol] = sw;
        __syncthreads();
        if (tid < 32) {
            double a2 = 0.0, a1 = 0.0;
            #pragma unroll
            for (int s = 0; s < 8; ++s) { a2 += s2d[s][tid]; a1 += s1d[s][tid]; }
            float w2f = (float)a2;
            g_w2[n0 + tid] = w2f;
            g_sw[n0 + tid] = (float)a1;
            atomicMax(&g_maxw2_bits, __float_as_int(w2f));
        }
    } else if (blk < PB_XSTATS) {
        // ---- xstats (FROZEN): fp64 per-row, one warp per row ----
        const int row = (blk - PB_WSTATS) * 8 + (tid >> 5);
        const int lane = tid & 31;
        const float* xr = x + (size_t)row * D_DIM;
        double p2 = 0.0, p1 = 0.0;
        for (int i = lane; i < D_DIM; i += 32) {
            float v = xr[i];
            p2 += (double)__fmul_rn(v, v);
            p1 += (double)v;
        }
        #pragma unroll
        for (int off = 16; off; off >>= 1) {
            p2 += __shfl_xor_sync(0xffffffffu, p2, off);
            p1 += __shfl_xor_sync(0xffffffffu, p1, off);
        }
        if (lane == 0) {
            float x2f = (float)p2;
            g_x2[row] = x2f;
            g_sx[row] = (float)p1;
            atomicMax(&g_maxx2_bits, __float_as_int(x2f));
        }
    } else if (blk < PB_CVTX) {
        // ---- convert_x (fragment layout verified in R9) ----
        int idx = (blk - PB_XSTATS) * 256 + tid;
        int lane = idx & 31;
        int kt = (idx >> 5) % (D_DIM / 16);
        int mt = (idx >> 5) / (D_DIM / 16);
        int r = mt * 16 + (lane >> 2);
        int c = kt * 16 + (lane & 3) * 2;
        const float* base = x + (size_t)r * D_DIM + c;
        uint4 o;
        o.x = pack_bf16(base[0], base[1]);
        o.y = pack_bf16(base[8 * D_DIM], base[8 * D_DIM + 1]);
        o.z = pack_bf16(base[8], base[9]);
        o.w = pack_bf16(base[8 * D_DIM + 8], base[8 * D_DIM + 9]);
        g_xfrag[idx] = o;
    } else {
        // ---- FUSED wT transpose + convert_w from one 32x32 tile of w ----
        int b = blk - PB_CVTX;
        int bx = b % 512, by = b / 512;     // bx: n-block(32), by: k-block(32)
        int tx = tid & 31, ty = tid >> 5;
        const int n0 = bx * 32, k0 = by * 32;
        #pragma unroll
        for (int i = 0; i < 4; ++i)
            tile[ty + i * 8][tx] = w[(size_t)(k0 + ty + i * 8) * M_COLS + n0 + tx];
        __syncthreads();
        #pragma unroll
        for (int i = 0; i < 4; ++i)
            g_wT[(size_t)(n0 + ty + i * 8) * D_DIM + k0 + tx] = tile[tx][ty + i * 8];
        {
            const int g = tid >> 5;                // 0..7
            const int lane = tid & 31;
            const int ntl = g & 3, ktl = g >> 2;
            const int kl = ktl * 16 + (lane & 3) * 2;
            const int nl = ntl * 8 + (lane >> 2);
            uint2 o;
            o.x = pack_bf16(tile[kl][nl], tile[kl + 1][nl]);
            o.y = pack_bf16(tile[kl + 8][nl], tile[kl + 9][nl]);
            const int nt = (n0 >> 3) + ntl;
            const int kt = (k0 >> 4) + ktl;
            g_wfrag[((size_t)nt * (D_DIM / 16) + kt) * 32 + lane] = o;
        }
    }
}

// ---------------------------------------------------------------------------
// Prune GEMM (R12, byte-identical): bf16 mma.sync, CTA 128x128, warp 64x32,
// 4-stage cp.async pipeline, bf16 staged coalesced stores, fp32 rowmins.
// ---------------------------------------------------------------------------
__global__ __launch_bounds__(256, 2)
void prune_gemm_kernel() {
    extern __shared__ char smem[];
    uint4* As = (uint4*)smem;                     // [4][512]
    uint2* Bs = (uint2*)(smem + 32768);           // [4][1024]

    const int tid = threadIdx.x;
    const int lane = tid & 31;
    const int wid = tid >> 5;
    const int wm = wid >> 2;          // 0..1
    const int wn = wid & 3;           // 0..3
    const int ntile = blockIdx.x, mtile = blockIdx.y;
    const int mtBase = mtile * 8;
    const int ntBase = ntile * 16;

    float c[4][4][4];
    #pragma unroll
    for (int i = 0; i < 4; ++i)
        #pragma unroll
        for (int j = 0; j < 4; ++j)
            #pragma unroll
            for (int r = 0; r < 4; ++r) c[i][j][r] = 0.f;

    auto issue = [&](int s) {
        const int buf = s & 3;
        #pragma unroll
        for (int r = 0; r < 2; ++r) {
            int ch = tid + r * 256;
            int mt = ch >> 6, kt = (ch >> 5) & 1, ln = ch & 31;
            const uint4* src = g_xfrag +
                ((size_t)(mtBase + mt) * (D_DIM / 16) + s * 2 + kt) * 32 + ln;
            CP_ASYNC16(smem_u32(&As[buf * 512 + ch]), src);
        }
        #pragma unroll
        for (int r = 0; r < 2; ++r) {
            int cb = tid + r * 256;
            int nt = cb >> 5, kt = (cb >> 4) & 1, lp = cb & 15;
            const uint2* src = g_wfrag +
                ((size_t)(ntBase + nt) * (D_DIM / 16) + s * 2 + kt) * 32 + lp * 2;
            CP_ASYNC16(smem_u32(&Bs[buf * 1024 + ((nt * 2 + kt) * 32 + lp * 2)]), src);
        }
        CP_COMMIT();
    };

    issue(0); issue(1); issue(2);

    for (int s = 0; s < NSTG; ++s) {
        if (s <= 13)      { CP_WAIT(2); }
        else if (s == 14) { CP_WAIT(1); }
        else              { CP_WAIT(0); }
        __syncthreads();
        if (s + 3 < NSTG) issue(s + 3);

        const int buf = s & 3;
        #pragma unroll
        for (int kt = 0; kt < 2; ++kt) {
            uint4 a[4];
            #pragma unroll
            for (int i = 0; i < 4; ++i)
                a[i] = As[buf * 512 + ((wm * 4 + i) * 2 + kt) * 32 + lane];
            uint2 b[4];
            #pragma unroll
            for (int j = 0; j < 4; ++j)
                b[j] = Bs[buf * 1024 + ((wn * 4 + j) * 2 + kt) * 32 + lane];
            #pragma unroll
            for (int i = 0; i < 4; ++i)
                #pragma unroll
                for (int j = 0; j < 4; ++j)
                    mma_bf16(c[i][j], a[i].x, a[i].y, a[i].z, a[i].w, b[j].x, b[j].y);
        }
    }
    __syncthreads();

    unsigned* st = (unsigned*)smem;             // [128][68] u32 (bf16x2)
    float* srm = (float*)(smem + 128 * 68 * 4); // [128]
    if (tid < 128) srm[tid] = FINF;
    __syncthreads();

    #pragma unroll
    for (int i = 0; i < 4; ++i) {
        int rl = wm * 64 + i * 16 + (lane >> 2);
        int gr = mtile * 128 + rl;
        float x2a = g_x2[gr], x2b = g_x2[gr + 8];
        float rmin0 = FINF, rmin1 = FINF;
        #pragma unroll
        for (int j = 0; j < 4; ++j) {
            int gc = ntile * 128 + wn * 32 + j * 8 + (lane & 3) * 2;
            float w2a = g_w2[gc], w2b = g_w2[gc + 1];
            float s0 = x2a + w2a - 2.f * c[i][j][0];
            float s1 = x2a + w2b - 2.f * c[i][j][1];
            float s2 = x2b + w2a - 2.f * c[i][j][2];
            float s3 = x2b + w2b - 2.f * c[i][j][3];
            int stcol = wn * 16 + j * 4 + (lane & 3);
            st[rl * 68 + stcol]       = pack_bf16(s0, s1);
            st[(rl + 8) * 68 + stcol] = pack_bf16(s2, s3);
            rmin0 = fminf(rmin0, fminf(s0, s1));
            rmin1 = fminf(rmin1, fminf(s2, s3));
        }
        rmin0 = fminf(rmin0, __shfl_xor_sync(0xffffffffu, rmin0, 1));
        rmin0 = fminf(rmin0, __shfl_xor_sync(0xffffffffu, rmin0, 2));
        rmin1 = fminf(rmin1, __shfl_xor_sync(0xffffffffu, rmin1, 1));
        rmin1 = fminf(rmin1, __shfl_xor_sync(0xffffffffu, rmin1, 2));
        if ((lane & 3) == 0) {
            atomicMin((int*)&srm[rl],     __float_as_int(fmaxf(rmin0, 0.f)));
            atomicMin((int*)&srm[rl + 8], __float_as_int(fmaxf(rmin1, 0.f)));
        }
    }
    __syncthreads();

    #pragma unroll
    for (int p = 0; p < 8; ++p) {
        int rl = p * 16 + (tid >> 4);
        uint4 v = *(uint4*)&st[rl * 68 + (tid & 15) * 4];
        *(uint4*)(g_approxh + (size_t)(mtile * 128 + rl) * (M_COLS / 2) +
                  ntile * 64 + (tid & 15) * 4) = v;
    }
    if (tid < 128)
        g_rowmin[(size_t)(mtile * 128 + tid) * NBLK + ntile] = srm[tid];
}

// ---------------------------------------------------------------------------
// FUSED collect + exact rescore (+ tail zeroing in block 0). 128 threads.
// Collect logic (warp 0) byte-identical to R16; rescore strided by 128.
// ---------------------------------------------------------------------------
__global__ __launch_bounds__(128)
void collect_rescore_kernel(const float* __restrict__ x,
                            const float* __restrict__ loc,
                            float* __restrict__ out, int out_size) {
    __shared__ int s_cand[CAP];
    __shared__ unsigned long long keys[CAP];
    __shared__ int s_cnt;
    const int q = blockIdx.x;
    const int tid = threadIdx.x;
    const int lane = tid & 31;

    if (q == 0) {   // tail zeroing (out poisoned by harness)
        const int main_elems = N_BMU * B_ROWS * 2;
        for (int i = main_elems + tid; i < out_size; i += 128) out[i] = 0.0f;
    }

    if (tid < 32) {
        float mx = __int_as_float(g_maxx2_bits);
        float mw = __int_as_float(g_maxw2_bits);
        float margin = 0.017f * sqrtf(mx * mw) + 0.25f;

        const float* rm = g_rowmin + (size_t)q * NBLK;
        float lmin = fminf(fminf(rm[lane], rm[lane + 32]),
                           fminf(rm[lane + 64], rm[lane + 96]));
        float cur = lmin, tau = FINF;
        #pragma unroll
        for (int r = 0; r < N_BMU; ++r) {
            float mn = cur;
            #pragma unroll
            for (int o = 16; o; o >>= 1)
                mn = fminf(mn, __shfl_xor_sync(0xffffffffu, mn, o));
            unsigned bal = __ballot_sync(0xffffffffu, cur == mn);
            if (lane == (__ffs(bal) - 1)) cur = FINF;
            tau = mn;
        }
        const float Tskip = tau + margin;
        const float Tq = Tskip + ((Tskip <= 2040.0f) ? 4.0f : 8.0f);

        float um0 = fminf(rm[2 * lane], rm[2 * lane + 1]);           // units 0..31
        float um1 = fminf(rm[64 + 2 * lane], rm[64 + 2 * lane + 1]); // units 32..63

        const uint4* rowp = (const uint4*)(g_approxh + (size_t)q * (M_COLS / 2));
        int cnt = 0;
        for (int u = 0; u < 64; ++u) {
            float umin = __shfl_sync(0xffffffffu, (u < 32) ? um0 : um1, u & 31);
            if (umin > Tskip) continue;            // warp-uniform skip
            uint4 v = rowp[u * 32 + lane];
            float2 f0 = unpack_bf16(v.x), f1 = unpack_bf16(v.y);
            float2 f2 = unpack_bf16(v.z), f3 = unpack_bf16(v.w);
            float f[8] = {f0.x, f0.y, f1.x, f1.y, f2.x, f2.y, f3.x, f3.y};
            #pragma unroll
            for (int j = 0; j < 8; ++j) {
                bool p = (f[j] <= Tq);
                unsigned msk = __ballot_sync(0xffffffffu, p);
                if (p) {
                    int off = cnt + __popc(msk & ((1u << lane) - 1u));
                    if (off < CAP) s_cand[off] = u * 256 + lane * 8 + j;
                }
                cnt += __popc(msk);
            }
        }
        if (lane == 0) s_cnt = cnt < CAP ? cnt : CAP;
    }
    __syncthreads();
    const int cnt = s_cnt;

    const float4* xr = (const float4*)(x + (size_t)q * D_DIM);
    const float x2 = g_x2[q], sx = g_sx[q];

    for (int t = tid; t < cnt; t += 128) {
        int m = s_cand[t];
        const float4* wr = (const float4*)(g_wT + (size_t)m * D_DIM);
        float acc = 0.f;
        for (int i = 0; i < D_DIM / 4; ++i) {   // FROZEN ascending FMA chain
            float4 a = xr[i], b = wr[i];
            acc = fmaf(a.x, b.x, acc);
            acc = fmaf(a.y, b.y, acc);
            acc = fmaf(a.z, b.z, acc);
            acc = fmaf(a.w, b.w, acc);
        }
        float t1 = __fsub_rn(x2, __fmul_rn(2.0f, acc));   // FROZEN epilogue
        t1 = __fadd_rn(t1, g_w2[m]);
        float ds = __fsub_rn(sx, g_sw[m]);
        t1 = __fadd_rn(t1, __fmul_rn(C1, ds));
        t1 = __fadd_rn(t1, C2);
        float dist = sqrtf(fmaxf(t1, 0.0f));
        keys[t] = ((unsigned long long)__float_as_uint(dist) << 32) | (unsigned)m;
    }
    __syncthreads();

    if (tid < 32) {
        #pragma unroll 1
        for (int r = 0; r < N_BMU; ++r) {
            unsigned long long lk = MAXKEY;
            int la = -1;
            for (int idx = lane; idx < cnt; idx += 32) {
                unsigned long long k = keys[idx];
                if (k < lk) { lk = k; la = idx; }
            }
            unsigned long long best = lk;
            #pragma unroll
            for (int o = 16; o; o >>= 1) {
                unsigned long long other = __shfl_xor_sync(0xffffffffu, best, o);
                if (other < best) best = other;
            }
            if (lk == best && la >= 0) keys[la] = MAXKEY;
            if (lane == r) {
                int m = (int)(best & 0xffffffffULL);
                out[((size_t)r * B_ROWS + q) * 2 + 0] = loc[m * 2 + 0];
                out[((size_t)r * B_ROWS + q) * 2 + 1] = loc[m * 2 + 1];
            }
            __syncwarp();
        }
    }
}

extern "C" void kernel_launch(void* const* d_in, const int* in_sizes, int n_in,
                              void* d_out, int out_size) {
    const float* x   = (const float*)d_in[0];
    const float* w   = (const float*)d_in[1];
    const float* loc = (const float*)d_in[2];
    float* out = (float*)d_out;

    cudaFuncSetAttribute(prune_gemm_kernel,
                         cudaFuncAttributeMaxDynamicSharedMemorySize, SMEM_GEMM);

    prep_kernel<<<PB_WTILE, 256>>>(x, w);
    prune_gemm_kernel<<<dim3(M_COLS / 128, B_ROWS / 128), 256, SMEM_GEMM>>>();
    collect_rescore_kernel<<<B_ROWS, 128>>>(x, loc, out, out_size);
}